// round 7
// baseline (speedup 1.0000x reference)
#include <cuda_runtime.h>
#include <cstdint>
#include <math.h>

#define S_LEN   2048
#define HIDDEN  4096
#define NHEADS  32
#define NKV     8
#define HD      128
#define QPK     4
#define QKV_N   6144          // NKV*(QPK+2)*HD
#define OUT_N   4096          // NHEADS*HD
#define SCALE_ATT 0.0078125f  // 1/HD

// ---------------- scratch (device globals: no allocations allowed) ----------
__device__ float g_qkv[S_LEN * QKV_N];        // 50 MB
__device__ float g_att[S_LEN * OUT_N];        // 32 MB
__device__ float g_cos[S_LEN * 64];
__device__ float g_sin[S_LEN * 64];
__device__ float g_hid_t[S_LEN * HIDDEN];     // tf32-rounded hidden
__device__ float g_wqkv_t[QKV_N * HIDDEN];    // tf32-rounded w_qkv
__device__ float g_wd_t[HIDDEN * HIDDEN];     // tf32-rounded w_dense

// ---------------- helpers ---------------------------------------------------
__device__ __forceinline__ uint32_t smem_u32(const void* p) {
    uint32_t a;
    asm("{ .reg .u64 t; cvta.to.shared.u64 t, %1; cvt.u32.u64 %0, t; }"
        : "=r"(a) : "l"(p));
    return a;
}
__device__ __forceinline__ uint32_t f2tf32(float x) {
    uint32_t u;
    asm("cvt.rna.tf32.f32 %0, %1;" : "=r"(u) : "f"(x));
    return u;
}
__device__ __forceinline__ void mma_16x8x8(float* c, const uint32_t* a,
                                           const uint32_t* b) {
    asm volatile(
        "mma.sync.aligned.m16n8k8.row.col.f32.tf32.tf32.f32 "
        "{%0,%1,%2,%3}, {%4,%5,%6,%7}, {%8,%9}, {%0,%1,%2,%3};\n"
        : "+f"(c[0]), "+f"(c[1]), "+f"(c[2]), "+f"(c[3])
        : "r"(a[0]), "r"(a[1]), "r"(a[2]), "r"(a[3]), "r"(b[0]), "r"(b[1]));
}
__device__ __forceinline__ void ldsm4(uint32_t addr, uint32_t& r0, uint32_t& r1,
                                      uint32_t& r2, uint32_t& r3) {
    asm volatile("ldmatrix.sync.aligned.m8n8.x4.shared.b16 {%0,%1,%2,%3}, [%4];"
                 : "=r"(r0), "=r"(r1), "=r"(r2), "=r"(r3) : "r"(addr));
}
__device__ __forceinline__ void cpa16(uint32_t dst, const void* src) {
    asm volatile("cp.async.cg.shared.global [%0], [%1], 16;" :: "r"(dst), "l"(src));
}
__device__ __forceinline__ void cpa_commit() {
    asm volatile("cp.async.commit_group;" ::: "memory");
}
template <int N>
__device__ __forceinline__ void cpa_wait() {
    asm volatile("cp.async.wait_group %0;" :: "n"(N) : "memory");
}

// ---------------------------------------------------------------------------
// tf32-rounding prep pass.
// ---------------------------------------------------------------------------
__global__ void round_tf32_kernel(const float4* __restrict__ in,
                                  float4* __restrict__ out, int n4)
{
    int i = blockIdx.x * blockDim.x + threadIdx.x;
    if (i >= n4) return;
    float4 v = in[i];
    out[i] = make_float4(__uint_as_float(f2tf32(v.x)), __uint_as_float(f2tf32(v.y)),
                         __uint_as_float(f2tf32(v.z)), __uint_as_float(f2tf32(v.w)));
}

// ---------------------------------------------------------------------------
// tf32 mma.sync GEMM, cp.async 3-stage pipeline (round-6 version, frozen).
// ---------------------------------------------------------------------------
#define GSTAGE 32768
#define GB_OFF 16384
__global__ __launch_bounds__(256, 2) void gemm_tf32_pipe(
    const float* __restrict__ A, const float* __restrict__ B,
    const float* __restrict__ bias, float* __restrict__ C,
    int N, int K)
{
    extern __shared__ char smem[];
    const uint32_t sb = smem_u32(smem);

    const int tid  = threadIdx.x;
    const int wid  = tid >> 5, lane = tid & 31;
    const int gid  = lane >> 2, tig = lane & 3;
    const int wm   = wid >> 2, wn = wid & 3;
    const int m0   = blockIdx.y * 128;
    const int n0   = blockIdx.x * 128;

    const int rowb = (lane & 7) + ((lane >> 4) << 3);
    const uint32_t swz7 = (uint32_t)(rowb & 7);
    const uint32_t chp  = (uint32_t)((lane >> 3) & 1);

    const int lr4 = tid >> 3;
    const int lc4 = tid & 7;
    const uint32_t ldst = ((uint32_t)((lc4 ^ (lr4 & 7))) << 4) + (uint32_t)lr4 * 128;
    const float* Ap = A + (size_t)(m0 + lr4) * K + lc4 * 4;
    const float* Bp = B + (size_t)(n0 + lr4) * K + lc4 * 4;

    float acc[4][4][4];
#pragma unroll
    for (int mi = 0; mi < 4; mi++)
#pragma unroll
        for (int nj = 0; nj < 4; nj++)
#pragma unroll
            for (int t = 0; t < 4; t++) acc[mi][nj][t] = 0.0f;

    const int KT = K >> 5;

#pragma unroll
    for (int s = 0; s < 2; s++) {
        const uint32_t base = sb + s * GSTAGE;
        const int kc = s * 32;
#pragma unroll
        for (int p = 0; p < 4; p++) {
            cpa16(base + ldst + p * 32 * 128, Ap + (size_t)(p * 32) * K + kc);
            cpa16(base + GB_OFF + ldst + p * 32 * 128, Bp + (size_t)(p * 32) * K + kc);
        }
        cpa_commit();
    }
    cpa_wait<1>();
    __syncthreads();

    for (int kt = 0; kt < KT; kt++) {
        if (kt + 2 < KT) {
            const uint32_t base = sb + ((kt + 2) % 3) * GSTAGE;
            const int kc = (kt + 2) * 32;
#pragma unroll
            for (int p = 0; p < 4; p++) {
                cpa16(base + ldst + p * 32 * 128, Ap + (size_t)(p * 32) * K + kc);
                cpa16(base + GB_OFF + ldst + p * 32 * 128, Bp + (size_t)(p * 32) * K + kc);
            }
        }
        cpa_commit();

        const uint32_t abase = sb + (kt % 3) * GSTAGE;
        const uint32_t bbase = abase + GB_OFF;
#pragma unroll
        for (int ks = 0; ks < 4; ks++) {
            const uint32_t lo = (((2u * ks + chp) ^ swz7) << 4);
            uint32_t a[4][4], b[4][2];
#pragma unroll
            for (int mi = 0; mi < 4; mi++) {
                uint32_t r0, r1, r2, r3;
                ldsm4(abase + (uint32_t)(wm * 64 + mi * 16 + rowb) * 128 + lo,
                      r0, r1, r2, r3);
                a[mi][0] = r0; a[mi][1] = r2; a[mi][2] = r1; a[mi][3] = r3;
            }
#pragma unroll
            for (int njp = 0; njp < 2; njp++) {
                uint32_t r0, r1, r2, r3;
                ldsm4(bbase + (uint32_t)(wn * 32 + njp * 16 + rowb) * 128 + lo,
                      r0, r1, r2, r3);
                b[2 * njp][0] = r0;     b[2 * njp][1] = r1;
                b[2 * njp + 1][0] = r2; b[2 * njp + 1][1] = r3;
            }
#pragma unroll
            for (int mi = 0; mi < 4; mi++)
#pragma unroll
                for (int nj = 0; nj < 4; nj++)
                    mma_16x8x8(acc[mi][nj], a[mi], b[nj]);
        }

        cpa_wait<1>();
        __syncthreads();
    }

    const float* bp = bias + n0 + wn * 32;
#pragma unroll
    for (int nj = 0; nj < 4; nj++) {
        int c = nj * 8 + 2 * tig;
        float2 bb = *(const float2*)(bp + c);
#pragma unroll
        for (int mi = 0; mi < 4; mi++) {
            int r = m0 + wm * 64 + mi * 16 + gid;
            float* dst = C + (size_t)r * N + n0 + wn * 32 + c;
            *(float2*)dst = make_float2(acc[mi][nj][0] + bb.x, acc[mi][nj][1] + bb.y);
            *(float2*)(dst + 8 * N) =
                make_float2(acc[mi][nj][2] + bb.x, acc[mi][nj][3] + bb.y);
        }
    }
}

// ---------------------------------------------------------------------------
// RoPE tables.
// ---------------------------------------------------------------------------
__global__ void cs_table_kernel(const int* __restrict__ positions)
{
    int idx = blockIdx.x * blockDim.x + threadIdx.x;
    if (idx >= S_LEN * 64) return;
    int i = idx & 63;
    int s = idx >> 6;
    float pos = (float)positions[s];
    double e = (double)(2 * i) / 128.0;
    float invf = (float)(1.0 / pow(1.0e6, e));
    float freq = pos * invf;
    g_cos[idx] = (float)cos((double)freq);
    g_sin[idx] = (float)sin((double)freq);
}

// RoPE + tf32 pre-round over ALL 6 slots: q0..q3,k get rope+round; v rounds
// only. Rounding here is bit-identical to converting at attention load.
__global__ void rope_round_kernel()
{
    int idx = blockIdx.x * blockDim.x + threadIdx.x;   // < S*NKV*6*64
    int i = idx & 63;
    int t = idx >> 6;
    int slot = t % 6;
    t /= 6;
    int kvh = t & 7;
    int s = t >> 3;
    size_t base = (size_t)s * QKV_N + kvh * 768 + slot * 128 + i;
    float x1 = g_qkv[base];
    float x2 = g_qkv[base + 64];
    if (slot < 5) {
        float c  = g_cos[(s << 6) | i];
        float sn = g_sin[(s << 6) | i];
        float y1 = x1 * c - x2 * sn;
        float y2 = x2 * c + x1 * sn;
        g_qkv[base]      = __uint_as_float(f2tf32(y1));
        g_qkv[base + 64] = __uint_as_float(f2tf32(y2));
    } else {
        g_qkv[base]      = __uint_as_float(f2tf32(x1));
        g_qkv[base + 64] = __uint_as_float(f2tf32(x2));
    }
}

// ---------------------------------------------------------------------------
// Tensor-core blocksparse flash attention, low-L1-traffic version.
// Q/K tiles: cp.async straight into swizzled smem (operands pre-rounded).
// V tile: LDG.128 + 4x4 shfl butterfly transpose + STS.128 (replaces 4x STS.32
// + 4x cvt per item). Ps overlays Ks. smem 96KB, 2 CTAs/SM.
// ---------------------------------------------------------------------------
#define ATT_QS 0
#define ATT_KS 32768
#define ATT_VT 65536
#define ATT_PS 32768           // overlays Ks
#define ATT_SMEM 98304

__global__ __launch_bounds__(128, 2) void attn_tc_kernel(float* __restrict__ out)
{
    extern __shared__ char smem[];
    const uint32_t sb = smem_u32(smem);
    const int tid = threadIdx.x, lane = tid & 31, w = tid >> 5;
    const int gid = lane >> 2, tig = lane & 3;
    const int qb = blockIdx.x, h = blockIdx.y;
    const int kvh = h >> 2, slot = h & 3;
    const int q0 = qb * 64;
    const size_t qoff = (size_t)kvh * 768 + slot * 128;
    const size_t koff = (size_t)kvh * 768 + 512;
    const size_t voff = (size_t)kvh * 768 + 640;

    const int rowb = (lane & 7) + ((lane >> 4) << 3);
    const uint32_t swz7 = (uint32_t)(rowb & 7);
    const uint32_t chp  = (uint32_t)((lane >> 3) & 1);
    const int Rw = w * 16;
    const int sub = tid & 3;

    // ---- Q tile via cp.async (pre-rounded tf32) ----
#pragma unroll
    for (int i = 0; i < 16; i++) {
        int idx = tid + i * 128;
        int r = idx >> 5, c = idx & 31;
        uint32_t dst = sb + ATT_QS + (uint32_t)r * 512 + ((uint32_t)(c >> 3) << 7)
                     + ((((uint32_t)(c & 7)) ^ (uint32_t)(r & 7)) << 4);
        cpa16(dst, g_qkv + (size_t)(q0 + r) * QKV_N + qoff + c * 4);
    }
    cpa_commit();

    float Oa[16][4];
#pragma unroll
    for (int nf = 0; nf < 16; nf++)
#pragma unroll
        for (int t = 0; t < 4; t++) Oa[nf][t] = 0.0f;
    float m0r = -1e30f, m1r = -1e30f, l0 = 0.0f, l1 = 0.0f;

    for (int kb = 0; kb <= qb; kb++) {
        if (!(((qb - kb) < 16) || (((kb + h + 1) & 7) == 0))) continue;
        const int k0 = kb * 64;
        __syncthreads();   // prior PV done reading Ps(=Ks region) / Vt

        // K tile via cp.async
#pragma unroll
        for (int i = 0; i < 16; i++) {
            int idx = tid + i * 128;
            int r = idx >> 5, c = idx & 31;
            uint32_t dst = sb + ATT_KS + (uint32_t)r * 512 + ((uint32_t)(c >> 3) << 7)
                         + ((((uint32_t)(c & 7)) ^ (uint32_t)(r & 7)) << 4);
            cpa16(dst, g_qkv + (size_t)(k0 + r) * QKV_N + koff + c * 4);
        }

        // V tile: register butterfly transpose -> [d][key], STS.128
#pragma unroll
        for (int i = 0; i < 16; i++) {
            int idx = tid + i * 128;
            int c  = idx >> 6;             // d-group 0..31
            int kg = (idx >> 2) & 15;      // key group (4 keys)
            int key = kg * 4 + sub;
            uint4 v = *(const uint4*)(g_qkv + (size_t)(k0 + key) * QKV_N + voff + c * 4);
            uint32_t r0 = v.x, r1 = v.y, r2 = v.z, r3 = v.w;
            // stage 1 (xor 1)
            uint32_t s1a = __shfl_xor_sync(0xffffffffu, (sub & 1) ? r0 : r1, 1);
            uint32_t s1b = __shfl_xor_sync(0xffffffffu, (sub & 1) ? r2 : r3, 1);
            if (sub & 1) { r0 = s1a; r2 = s1b; } else { r1 = s1a; r3 = s1b; }
            // stage 2 (xor 2)
            uint32_t s2a = __shfl_xor_sync(0xffffffffu, (sub & 2) ? r0 : r2, 2);
            uint32_t s2b = __shfl_xor_sync(0xffffffffu, (sub & 2) ? r1 : r3, 2);
            if (sub & 2) { r0 = s2a; r1 = s2b; } else { r2 = s2a; r3 = s2b; }
            // now rj = V[kg*4+j][d], d = 4c+sub
            int d = 4 * c + sub;
            uint32_t off = (uint32_t)d * 256 + ((uint32_t)(kg >> 3) << 7)
                         + ((((uint32_t)(kg & 7)) ^ (uint32_t)(d & 7)) << 4);
            *(uint4*)(smem + ATT_VT + off) = make_uint4(r0, r1, r2, r3);
        }
        cpa_commit();
        cpa_wait<0>();
        __syncthreads();

        // ---- S = Q @ K^T ----
        float Sa[8][4];
#pragma unroll
        for (int nj = 0; nj < 8; nj++)
#pragma unroll
            for (int t = 0; t < 4; t++) Sa[nj][t] = 0.0f;
#pragma unroll
        for (int ks2 = 0; ks2 < 16; ks2++) {
            uint32_t ch = 2u * ks2 + chp;
            uint32_t hi = (ch >> 3) << 7, lo = ((ch & 7) ^ swz7) << 4;
            uint32_t r0, r1, r2, r3;
            ldsm4(sb + ATT_QS + (uint32_t)(Rw + rowb) * 512 + hi + lo, r0, r1, r2, r3);
            uint32_t Af[4] = {r0, r2, r1, r3};
#pragma unroll
            for (int njp = 0; njp < 4; njp++) {
                uint32_t b0, b1, b2, b3;
                ldsm4(sb + ATT_KS + (uint32_t)(njp * 16 + rowb) * 512 + hi + lo,
                      b0, b1, b2, b3);
                uint32_t B0[2] = {b0, b1}, B1[2] = {b2, b3};
                mma_16x8x8(Sa[2 * njp], Af, B0);
                mma_16x8x8(Sa[2 * njp + 1], Af, B1);
            }
        }
        __syncthreads();   // all warps done reading Ks before Ps overlays it

        const bool diag = (kb == qb);
        const int r0l = Rw + gid, r1l = r0l + 8;
        float mx0 = -1e30f, mx1 = -1e30f;
#pragma unroll
        for (int nj = 0; nj < 8; nj++) {
            int c0 = nj * 8 + 2 * tig;
            float v0 = Sa[nj][0] * SCALE_ATT;
            float v1 = Sa[nj][1] * SCALE_ATT;
            float v2 = Sa[nj][2] * SCALE_ATT;
            float v3 = Sa[nj][3] * SCALE_ATT;
            if (diag) {
                if (c0 > r0l)     v0 = -1e30f;
                if (c0 + 1 > r0l) v1 = -1e30f;
                if (c0 > r1l)     v2 = -1e30f;
                if (c0 + 1 > r1l) v3 = -1e30f;
            }
            Sa[nj][0] = v0; Sa[nj][1] = v1; Sa[nj][2] = v2; Sa[nj][3] = v3;
            mx0 = fmaxf(mx0, fmaxf(v0, v1));
            mx1 = fmaxf(mx1, fmaxf(v2, v3));
        }
        mx0 = fmaxf(mx0, __shfl_xor_sync(0xffffffffu, mx0, 1));
        mx0 = fmaxf(mx0, __shfl_xor_sync(0xffffffffu, mx0, 2));
        mx1 = fmaxf(mx1, __shfl_xor_sync(0xffffffffu, mx1, 1));
        mx1 = fmaxf(mx1, __shfl_xor_sync(0xffffffffu, mx1, 2));
        const float mn0 = fmaxf(m0r, mx0), mn1 = fmaxf(m1r, mx1);
        const float corr0 = __expf(m0r - mn0), corr1 = __expf(m1r - mn1);
        float s0 = 0.0f, s1 = 0.0f;
#pragma unroll
        for (int nj = 0; nj < 8; nj++) {
            float p0 = __expf(Sa[nj][0] - mn0);
            float p1 = __expf(Sa[nj][1] - mn0);
            float p2 = __expf(Sa[nj][2] - mn1);
            float p3 = __expf(Sa[nj][3] - mn1);
            s0 += p0 + p1; s1 += p2 + p3;
            int col = nj * 8 + 2 * tig;
            uint32_t ch = (uint32_t)col >> 2;
            uint32_t base = ((ch >> 3) << 7) + (((ch & 7) ^ (uint32_t)(r0l & 7)) << 4)
                          + ((uint32_t)col & 3) * 4;
            *(uint2*)(smem + ATT_PS + (uint32_t)r0l * 256 + base) =
                make_uint2(f2tf32(p0), f2tf32(p1));
            *(uint2*)(smem + ATT_PS + (uint32_t)r1l * 256 + base) =
                make_uint2(f2tf32(p2), f2tf32(p3));
        }
        s0 += __shfl_xor_sync(0xffffffffu, s0, 1);
        s0 += __shfl_xor_sync(0xffffffffu, s0, 2);
        s1 += __shfl_xor_sync(0xffffffffu, s1, 1);
        s1 += __shfl_xor_sync(0xffffffffu, s1, 2);
        l0 = l0 * corr0 + s0; l1 = l1 * corr1 + s1;
        m0r = mn0; m1r = mn1;
#pragma unroll
        for (int nf = 0; nf < 16; nf++) {
            Oa[nf][0] *= corr0; Oa[nf][1] *= corr0;
            Oa[nf][2] *= corr1; Oa[nf][3] *= corr1;
        }
        __syncthreads();   // Ps visible to all warps

        // ---- O += P @ V ----
#pragma unroll
        for (int kss = 0; kss < 8; kss++) {
            uint32_t ch = 2u * kss + chp;
            uint32_t hi = (ch >> 3) << 7, lo = ((ch & 7) ^ swz7) << 4;
            uint32_t r0, r1, r2, r3;
            ldsm4(sb + ATT_PS + (uint32_t)(Rw + rowb) * 256 + hi + lo, r0, r1, r2, r3);
            uint32_t Af[4] = {r0, r2, r1, r3};
#pragma unroll
            for (int nfp = 0; nfp < 8; nfp++) {
                uint32_t b0, b1, b2, b3;
                ldsm4(sb + ATT_VT + (uint32_t)(nfp * 16 + rowb) * 256 + hi + lo,
                      b0, b1, b2, b3);
                uint32_t B0[2] = {b0, b1}, B1[2] = {b2, b3};
                mma_16x8x8(Oa[2 * nfp], Af, B0);
                mma_16x8x8(Oa[2 * nfp + 1], Af, B1);
            }
        }
    }

    const float i0 = 1.0f / l0, i1 = 1.0f / l1;
    const int gr0 = q0 + Rw + gid;
    float* d0 = out + (size_t)gr0 * OUT_N + h * HD;
    float* d1 = d0 + (size_t)8 * OUT_N;
#pragma unroll
    for (int nf = 0; nf < 16; nf++) {
        int c = nf * 8 + 2 * tig;
        *(float2*)(d0 + c) =
            make_float2(__uint_as_float(f2tf32(Oa[nf][0] * i0)),
                        __uint_as_float(f2tf32(Oa[nf][1] * i0)));
        *(float2*)(d1 + c) =
            make_float2(__uint_as_float(f2tf32(Oa[nf][2] * i1)),
                        __uint_as_float(f2tf32(Oa[nf][3] * i1)));
    }
}

// ---------------------------------------------------------------------------
extern "C" void kernel_launch(void* const* d_in, const int* in_sizes, int n_in,
                              void* d_out, int out_size)
{
    const int*   positions = (const int*)  d_in[0];
    const float* hidden    = (const float*)d_in[1];
    const float* w_qkv     = (const float*)d_in[2];
    const float* b_qkv     = (const float*)d_in[3];
    const float* w_dense   = (const float*)d_in[4];
    const float* b_dense   = (const float*)d_in[5];
    float* out = (float*)d_out;

    float *qkv_p, *att_p, *hid_t, *wqkv_t, *wd_t;
    cudaGetSymbolAddress((void**)&qkv_p, g_qkv);
    cudaGetSymbolAddress((void**)&att_p, g_att);
    cudaGetSymbolAddress((void**)&hid_t, g_hid_t);
    cudaGetSymbolAddress((void**)&wqkv_t, g_wqkv_t);
    cudaGetSymbolAddress((void**)&wd_t, g_wd_t);

    cudaFuncSetAttribute(attn_tc_kernel,
                         cudaFuncAttributeMaxDynamicSharedMemorySize, ATT_SMEM);
    cudaFuncSetAttribute(gemm_tf32_pipe,
                         cudaFuncAttributeMaxDynamicSharedMemorySize, 3 * GSTAGE);

    // 0) pre-round GEMM operands to tf32
    {
        int n4;
        n4 = S_LEN * HIDDEN / 4;
        round_tf32_kernel<<<(n4 + 255) / 256, 256>>>((const float4*)hidden,
                                                     (float4*)hid_t, n4);
        n4 = QKV_N * HIDDEN / 4;
        round_tf32_kernel<<<(n4 + 255) / 256, 256>>>((const float4*)w_qkv,
                                                     (float4*)wqkv_t, n4);
        n4 = HIDDEN * HIDDEN / 4;
        round_tf32_kernel<<<(n4 + 255) / 256, 256>>>((const float4*)w_dense,
                                                     (float4*)wd_t, n4);
    }
    // 1) QKV = hidden @ w_qkv^T + b_qkv
    gemm_tf32_pipe<<<dim3(QKV_N / 128, S_LEN / 128), 256, 3 * GSTAGE>>>(
        hid_t, wqkv_t, b_qkv, qkv_p, QKV_N, HIDDEN);
    // 2) RoPE + tf32 pre-round of q,k,v
    cs_table_kernel<<<(S_LEN * 64 + 255) / 256, 256>>>(positions);
    rope_round_kernel<<<(S_LEN * NKV * 6 * 64) / 256, 256>>>();
    // 3) blocksparse attention (tensor cores)
    attn_tc_kernel<<<dim3(32, 32), 128, ATT_SMEM>>>(att_p);
    // 4) out = g_att @ w_dense^T + b_dense
    gemm_tf32_pipe<<<dim3(OUT_N / 128, S_LEN / 128), 256, 3 * GSTAGE>>>(
        att_p, wd_t, b_dense, out, OUT_N, HIDDEN);
}